// round 17
// baseline (speedup 1.0000x reference)
#include <cuda_runtime.h>
#include <cuda_fp16.h>
#include <math.h>

#define NND 100000
#define NE  3200000
#define LTOK 64
#define HID 16
#define EF  5
#define CAP 32            // fixed bucket capacity per src node

struct __align__(32) V8 { uint4 a, b; };
struct __align__(32) F8 { float4 a, b; };

// ---- scratch (device globals; no allocation allowed) ----
__device__ int   g_deg[NND];
__device__ int   g_csr[NND * CAP]; // dst buckets, fixed stride (row = 128B aligned)
__device__ F8    g_Ms1[NND * 2];   // UNSCALED X@w1+b1
__device__ F8    g_Ms2[NND * 2];   // pre-scaled by dinv
__device__ V8    g_Ah[NND];
__device__ V8    g_Bh[NND];
__device__ __align__(16) unsigned char g_b8[NND];

__device__ __forceinline__ V8 ldg256u(const V8* p) {
    V8 r;
    asm volatile("ld.global.nc.v8.b32 {%0,%1,%2,%3,%4,%5,%6,%7}, [%8];"
        : "=r"(r.a.x), "=r"(r.a.y), "=r"(r.a.z), "=r"(r.a.w),
          "=r"(r.b.x), "=r"(r.b.y), "=r"(r.b.z), "=r"(r.b.w)
        : "l"(p));
    return r;
}
__device__ __forceinline__ F8 ldg256f(const F8* p) {
    F8 r;
    asm volatile("ld.global.nc.v8.f32 {%0,%1,%2,%3,%4,%5,%6,%7}, [%8];"
        : "=f"(r.a.x), "=f"(r.a.y), "=f"(r.a.z), "=f"(r.a.w),
          "=f"(r.b.x), "=f"(r.b.y), "=f"(r.b.z), "=f"(r.b.w)
        : "l"(p));
    return r;
}
__device__ __forceinline__ void stg256f(F8* p, const float* v) {
    asm volatile("st.global.v8.f32 [%0], {%1,%2,%3,%4,%5,%6,%7,%8};"
        :: "l"(p), "f"(v[0]), "f"(v[1]), "f"(v[2]), "f"(v[3]),
           "f"(v[4]), "f"(v[5]), "f"(v[6]), "f"(v[7]) : "memory");
}
__device__ __forceinline__ void stg256u(V8* p, const unsigned* v) {
    asm volatile("st.global.v8.b32 [%0], {%1,%2,%3,%4,%5,%6,%7,%8};"
        :: "l"(p), "r"(v[0]), "r"(v[1]), "r"(v[2]), "r"(v[3]),
           "r"(v[4]), "r"(v[5]), "r"(v[6]), "r"(v[7]) : "memory");
}
__device__ __forceinline__ float dinv_of(int deg) {
    return rsqrtf((float)deg + 1.0f + 1e-8f);
}

// ---------------- K0: zero degree + pack batch->u8 ----------------
__global__ void k_zero_small(const int* __restrict__ batch) {
    cudaTriggerProgrammaticLaunchCompletion();
    int i = blockIdx.x * blockDim.x + threadIdx.x;
    if (i < NND) {
        g_deg[i] = 0;
        g_b8[i] = (unsigned char)batch[i];
    }
}

// ---------------- K1: degree + direct CSR bucket build ----------------
#define DC_BLOCKS 296
#define DC_THREADS 512
__global__ void __launch_bounds__(DC_THREADS) k_build(const int* __restrict__ ei) {
    cudaTriggerProgrammaticLaunchCompletion();
    cudaGridDependencySynchronize();   // wait k_zero (b8 table, deg=0)
    extern __shared__ unsigned char s_b8[];   // NND bytes
    {
        const int4* src = reinterpret_cast<const int4*>(g_b8);
        int4* dst = reinterpret_cast<int4*>(s_b8);
        for (int j = threadIdx.x; j < NND / 16; j += DC_THREADS) dst[j] = src[j];
    }
    __syncthreads();

    const int NCH = NE / 8;                       // 400000 chunks of 8 edges
    const int STRIDE = DC_BLOCKS * DC_THREADS;
    const int ITERS = (NCH + STRIDE - 1) / STRIDE;
    int gtid = blockIdx.x * DC_THREADS + threadIdx.x;

    for (int it = 0; it < ITERS; it++) {
        int i = gtid + it * STRIDE;
        if (i >= NCH) break;
        int base_e = i * 8;
        V8 sa = ldg256u(reinterpret_cast<const V8*>(ei + base_e));
        V8 da = ldg256u(reinterpret_cast<const V8*>(ei + NE + base_e));
        int sv[8] = {(int)sa.a.x, (int)sa.a.y, (int)sa.a.z, (int)sa.a.w,
                     (int)sa.b.x, (int)sa.b.y, (int)sa.b.z, (int)sa.b.w};
        int dv[8] = {(int)da.a.x, (int)da.a.y, (int)da.a.z, (int)da.a.w,
                     (int)da.b.x, (int)da.b.y, (int)da.b.z, (int)da.b.w};
#pragma unroll
        for (int j = 0; j < 8; j++) {
            if (s_b8[sv[j]] == s_b8[dv[j]]) {
                int pos = atomicAdd(&g_deg[sv[j]], 1);
                if (pos < CAP) g_csr[sv[j] * CAP + pos] = dv[j];
            }
        }
    }
}

// ---------------- K2: encode (independent stream): UNSCALED M1 ----------------
__global__ void k_encode(const int* __restrict__ seq, const float* __restrict__ xcov,
                         const float* __restrict__ embed, const float* __restrict__ w1,
                         const float* __restrict__ b1) {
    __shared__ float s_emb[6 * 16];
    __shared__ float s_w1[17 * 16];
    __shared__ float s_b1[16];
    int t = threadIdx.x;
    for (int j = t; j < 96; j += blockDim.x) s_emb[j] = embed[j];
    for (int j = t; j < 272; j += blockDim.x) s_w1[j] = w1[j];
    if (t < 16) s_b1[t] = b1[t];
    __syncthreads();

    int n = blockIdx.x * blockDim.x + t;
    if (n >= NND) return;

    int c1 = 0, c2 = 0, c3 = 0, c4 = 0, c5 = 0;
    const V8* tp = reinterpret_cast<const V8*>(seq + (long)n * LTOK);
#pragma unroll
    for (int i = 0; i < 8; i++) {
        V8 v = ldg256u(tp + i);
        int tok[8] = {(int)v.a.x, (int)v.a.y, (int)v.a.z, (int)v.a.w,
                      (int)v.b.x, (int)v.b.y, (int)v.b.z, (int)v.b.w};
#pragma unroll
        for (int j = 0; j < 8; j++) {
            int tk = tok[j];
            c1 += (tk == 1); c2 += (tk == 2); c3 += (tk == 3);
            c4 += (tk == 4); c5 += (tk == 5);
        }
    }
    int nz = c1 + c2 + c3 + c4 + c5;
    float inv = 1.0f / fmaxf((float)nz, 1.0f);
    float f1 = c1 * inv, f2 = c2 * inv, f3 = c3 * inv, f4 = c4 * inv, f5 = c5 * inv;

    float x[17];
#pragma unroll
    for (int k = 0; k < 16; k++) {
        x[k] = f1 * s_emb[16 + k] + f2 * s_emb[32 + k] + f3 * s_emb[48 + k]
             + f4 * s_emb[64 + k] + f5 * s_emb[80 + k];
    }
    x[16] = xcov[n];

    float m[16];
#pragma unroll
    for (int k = 0; k < 16; k++) {
        float s = s_b1[k];
#pragma unroll
        for (int j = 0; j < 17; j++) s += x[j] * s_w1[j * 16 + k];
        m[k] = s;   // UNSCALED
    }
    stg256f(&g_Ms1[2 * n + 0], m);
    stg256f(&g_Ms1[2 * n + 1], m + 8);
}

// ---------------- K3: fin1: unrolled prefetch gather; Ms2 = dinv*(h@w2+b2) ----------------
__global__ void __launch_bounds__(256) k_fin1(const float* __restrict__ w2,
                                              const float* __restrict__ b2) {
    cudaTriggerProgrammaticLaunchCompletion();
    __shared__ float sW[16 * 16];
    __shared__ float sb[16];
    int t = threadIdx.x;
    for (int j = t; j < 256; j += blockDim.x) sW[j] = w2[j];
    if (t < 16) sb[t] = b2[t];
    __syncthreads();
    cudaGridDependencySynchronize();

    int n = blockIdx.x * blockDim.x + t;
    if (n >= NND) return;
    int degv = g_deg[n];
    int cnt = min(degv, CAP);
    int start = n * CAP;

    // one v8 load gets the first 8 neighbor IDs (covers virtually all nodes)
    V8 bkt = ldg256u(reinterpret_cast<const V8*>(&g_csr[start]));
    int ds[8] = {(int)bkt.a.x, (int)bkt.a.y, (int)bkt.a.z, (int)bkt.a.w,
                 (int)bkt.b.x, (int)bkt.b.y, (int)bkt.b.z, (int)bkt.b.w};

    // all deg gathers issue together (independent)
    float cs[8];
#pragma unroll
    for (int k = 0; k < 8; k++)
        cs[k] = (k < cnt) ? dinv_of(__ldg(&g_deg[ds[k]])) : 0.f;

    float acc[16];
#pragma unroll
    for (int k = 0; k < 16; k++) acc[k] = 0.f;

    // unrolled predicated Ms gathers — addresses known upfront, loads batch
#pragma unroll
    for (int k = 0; k < 8; k++) {
        if (k < cnt) {
            F8 ra = ldg256f(&g_Ms1[2 * ds[k] + 0]);
            F8 rb = ldg256f(&g_Ms1[2 * ds[k] + 1]);
            const float* f0 = reinterpret_cast<const float*>(&ra);
            const float* f1 = reinterpret_cast<const float*>(&rb);
            float c = cs[k];
#pragma unroll
            for (int i = 0; i < 8; i++) acc[i] += c * f0[i];
#pragma unroll
            for (int i = 0; i < 8; i++) acc[8 + i] += c * f1[i];
        }
    }
    // rare tail (cnt > 8)
    for (int k = 8; k < cnt; k++) {
        int d = __ldg(&g_csr[start + k]);
        float c = dinv_of(__ldg(&g_deg[d]));
        F8 ra = ldg256f(&g_Ms1[2 * d + 0]);
        F8 rb = ldg256f(&g_Ms1[2 * d + 1]);
        const float* f0 = reinterpret_cast<const float*>(&ra);
        const float* f1 = reinterpret_cast<const float*>(&rb);
#pragma unroll
        for (int i = 0; i < 8; i++) acc[i] += c * f0[i];
#pragma unroll
        for (int i = 0; i < 8; i++) acc[8 + i] += c * f1[i];
    }

    float dinv = dinv_of(degv);
    float d2 = dinv * dinv;
    F8 ma = ldg256f(&g_Ms1[2 * n + 0]);
    F8 mb = ldg256f(&g_Ms1[2 * n + 1]);
    const float* mv0 = reinterpret_cast<const float*>(&ma);
    const float* mv1 = reinterpret_cast<const float*>(&mb);
    float h[16];
#pragma unroll
    for (int k = 0; k < 8; k++) h[k] = fmaxf(dinv * acc[k] + d2 * mv0[k], 0.f);
#pragma unroll
    for (int k = 0; k < 8; k++) h[8 + k] = fmaxf(dinv * acc[8 + k] + d2 * mv1[k], 0.f);

    float m2[16];
#pragma unroll
    for (int k = 0; k < 16; k++) {
        float s = sb[k];
#pragma unroll
        for (int j = 0; j < 16; j++) s += h[j] * sW[j * 16 + k];
        m2[k] = s * dinv;   // pre-scaled
    }
    stg256f(&g_Ms2[2 * n + 0], m2);
    stg256f(&g_Ms2[2 * n + 1], m2 + 8);
}

// ---------------- K4: fin2: unrolled prefetch gather; A,B fp16 ----------------
__global__ void __launch_bounds__(256) k_fin2(const float* __restrict__ we1,
                                              const float* __restrict__ be1) {
    cudaTriggerProgrammaticLaunchCompletion();
    __shared__ float sW[32 * 16];
    __shared__ float sb[16];
    int t = threadIdx.x;
    for (int j = t; j < 512; j += blockDim.x) sW[j] = we1[j];
    if (t < 16) sb[t] = be1[t];
    __syncthreads();
    cudaGridDependencySynchronize();

    int n = blockIdx.x * blockDim.x + t;
    if (n >= NND) return;
    int degv = g_deg[n];
    int cnt = min(degv, CAP);
    int start = n * CAP;

    V8 bkt = ldg256u(reinterpret_cast<const V8*>(&g_csr[start]));
    int ds[8] = {(int)bkt.a.x, (int)bkt.a.y, (int)bkt.a.z, (int)bkt.a.w,
                 (int)bkt.b.x, (int)bkt.b.y, (int)bkt.b.z, (int)bkt.b.w};

    float acc[16];
#pragma unroll
    for (int k = 0; k < 16; k++) acc[k] = 0.f;

#pragma unroll
    for (int k = 0; k < 8; k++) {
        if (k < cnt) {
            F8 ra = ldg256f(&g_Ms2[2 * ds[k] + 0]);
            F8 rb = ldg256f(&g_Ms2[2 * ds[k] + 1]);
            const float* f0 = reinterpret_cast<const float*>(&ra);
            const float* f1 = reinterpret_cast<const float*>(&rb);
#pragma unroll
            for (int i = 0; i < 8; i++) acc[i] += f0[i];
#pragma unroll
            for (int i = 0; i < 8; i++) acc[8 + i] += f1[i];
        }
    }
    for (int k = 8; k < cnt; k++) {
        int d = __ldg(&g_csr[start + k]);
        F8 ra = ldg256f(&g_Ms2[2 * d + 0]);
        F8 rb = ldg256f(&g_Ms2[2 * d + 1]);
        const float* f0 = reinterpret_cast<const float*>(&ra);
        const float* f1 = reinterpret_cast<const float*>(&rb);
#pragma unroll
        for (int i = 0; i < 8; i++) acc[i] += f0[i];
#pragma unroll
        for (int i = 0; i < 8; i++) acc[8 + i] += f1[i];
    }

    float dinv = dinv_of(degv);
    F8 ma = ldg256f(&g_Ms2[2 * n + 0]);
    F8 mb = ldg256f(&g_Ms2[2 * n + 1]);
    const float* mv0 = reinterpret_cast<const float*>(&ma);
    const float* mv1 = reinterpret_cast<const float*>(&mb);
    float h[16];
#pragma unroll
    for (int k = 0; k < 8; k++) h[k] = fmaxf(dinv * (acc[k] + mv0[k]), 0.f);
#pragma unroll
    for (int k = 0; k < 8; k++) h[8 + k] = fmaxf(dinv * (acc[8 + k] + mv1[k]), 0.f);

    float av[16], bv[16];
#pragma unroll
    for (int k = 0; k < 16; k++) {
        float sa = sb[k];
        float sbv = 0.f;
#pragma unroll
        for (int j = 0; j < 16; j++) {
            sa  += h[j] * sW[j * 16 + k];
            sbv += h[j] * sW[(16 + j) * 16 + k];
        }
        av[k] = sa; bv[k] = sbv;
    }
    unsigned wa[8], wb[8];
#pragma unroll
    for (int i = 0; i < 8; i++) {
        __half2 pa = __floats2half2_rn(av[2 * i], av[2 * i + 1]);
        __half2 pb = __floats2half2_rn(bv[2 * i], bv[2 * i + 1]);
        wa[i] = *reinterpret_cast<unsigned*>(&pa);
        wb[i] = *reinterpret_cast<unsigned*>(&pb);
    }
    stg256u(&g_Ah[n], wa);
    stg256u(&g_Bh[n], wb);
}

// ---------------- K5: edge MLP output (2 edges/thread, half2, input streaming pre-sync) ----------------
#define EO_TB 256
__global__ void __launch_bounds__(EO_TB, 4) k_edge_out(
    const int* __restrict__ ei, const float* __restrict__ eattr,
    const float* __restrict__ we1, const float* __restrict__ we2,
    const float* __restrict__ be2, float* __restrict__ out) {
    __shared__ __half2 sWc2[5 * 8];
    __shared__ __half2 sW22[8];
    __shared__ float sb2;
    int t = threadIdx.x;
    if (t < 40) {
        int r = t >> 3, kk = t & 7;
        sWc2[t] = __floats2half2_rn(we1[(32 + r) * 16 + 2 * kk],
                                    we1[(32 + r) * 16 + 2 * kk + 1]);
    }
    if (t < 8) sW22[t] = __floats2half2_rn(we2[2 * t], we2[2 * t + 1]);
    if (t == 0) sb2 = be2[0];
    __syncthreads();

    int gt = blockIdx.x * EO_TB + t;
    int base_e = gt * 2;
    int2 s2 = *reinterpret_cast<const int2*>(ei + base_e);
    int2 d2 = *reinterpret_cast<const int2*>(ei + NE + base_e);
    float ea[10];
    const float2* ep = reinterpret_cast<const float2*>(eattr + (long)base_e * EF);
#pragma unroll
    for (int q = 0; q < 5; q++) {
        float2 v = ep[q];
        ea[2 * q + 0] = v.x;
        ea[2 * q + 1] = v.y;
    }

    cudaGridDependencySynchronize();

    V8 pa0 = ldg256u(&g_Ah[s2.x]);
    V8 pb0 = ldg256u(&g_Bh[d2.x]);
    V8 pa1 = ldg256u(&g_Ah[s2.y]);
    V8 pb1 = ldg256u(&g_Bh[d2.y]);

    const __half2 z2 = __float2half2_rn(0.f);
    float res[2];
#pragma unroll
    for (int j = 0; j < 2; j++) {
        const V8& PA = j ? pa1 : pa0;
        const V8& PB = j ? pb1 : pb0;
        const unsigned aw[8] = {PA.a.x, PA.a.y, PA.a.z, PA.a.w, PA.b.x, PA.b.y, PA.b.z, PA.b.w};
        const unsigned bw[8] = {PB.a.x, PB.a.y, PB.a.z, PB.a.w, PB.b.x, PB.b.y, PB.b.z, PB.b.w};
        __half2 h2[8];
#pragma unroll
        for (int i = 0; i < 8; i++) {
            h2[i] = __hadd2(*reinterpret_cast<const __half2*>(&aw[i]),
                            *reinterpret_cast<const __half2*>(&bw[i]));
        }
#pragma unroll
        for (int r = 0; r < EF; r++) {
            __half2 ev = __float2half2_rn(ea[5 * j + r]);
#pragma unroll
            for (int i = 0; i < 8; i++) h2[i] = __hfma2(ev, sWc2[r * 8 + i], h2[i]);
        }
        __half2 acc0 = z2, acc1 = z2;
#pragma unroll
        for (int i = 0; i < 4; i++) {
            acc0 = __hfma2(__hmax2(h2[i], z2),     sW22[i],     acc0);
            acc1 = __hfma2(__hmax2(h2[4 + i], z2), sW22[4 + i], acc1);
        }
        float2 f0 = __half22float2(acc0);
        float2 f1 = __half22float2(acc1);
        res[j] = sb2 + ((f0.x + f0.y) + (f1.x + f1.y));
    }
    *reinterpret_cast<float2*>(out + base_e) = make_float2(res[0], res[1]);
}

extern "C" void kernel_launch(void* const* d_in, const int* in_sizes, int n_in,
                              void* d_out, int out_size) {
    const int*   seq   = (const int*)d_in[0];
    const float* xcov  = (const float*)d_in[1];
    const int*   ei    = (const int*)d_in[2];
    const float* eattr = (const float*)d_in[3];
    const int*   batch = (const int*)d_in[4];
    const float* embed = (const float*)d_in[5];
    const float* w1    = (const float*)d_in[6];
    const float* b1    = (const float*)d_in[7];
    const float* w2    = (const float*)d_in[8];
    const float* b2    = (const float*)d_in[9];
    const float* we1   = (const float*)d_in[10];
    const float* be1   = (const float*)d_in[11];
    const float* we2   = (const float*)d_in[12];
    const float* be2   = (const float*)d_in[13];
    float* out = (float*)d_out;

    static cudaStream_t s1;
    static cudaEvent_t ev_fork, ev_join;
    static bool init_done = false;
    if (!init_done) {
        cudaFuncSetAttribute((const void*)k_build,
                             cudaFuncAttributeMaxDynamicSharedMemorySize, NND);
        cudaStreamCreateWithFlags(&s1, cudaStreamNonBlocking);
        cudaEventCreateWithFlags(&ev_fork, cudaEventDisableTiming);
        cudaEventCreateWithFlags(&ev_join, cudaEventDisableTiming);
        init_done = true;
    }

    const int TB = 256;
    const int nb_e2 = NE / (EO_TB * 2);           // 6250
    const int nb_n = (NND + TB - 1) / TB;         // 391

    cudaLaunchAttribute pdl;
    pdl.id = cudaLaunchAttributeProgrammaticStreamSerialization;
    pdl.val.programmaticStreamSerializationAllowed = 1;

    // fork: encode runs concurrently with zero + build
    cudaEventRecord(ev_fork, 0);
    cudaStreamWaitEvent(s1, ev_fork, 0);
    k_encode<<<nb_n, TB, 0, s1>>>(seq, xcov, embed, w1, b1);
    cudaEventRecord(ev_join, s1);

    k_zero_small<<<nb_n, TB>>>(batch);

    {
        cudaLaunchConfig_t cfg = {};
        cfg.gridDim = dim3(DC_BLOCKS); cfg.blockDim = dim3(DC_THREADS);
        cfg.dynamicSmemBytes = NND; cfg.stream = 0;
        cfg.attrs = &pdl; cfg.numAttrs = 1;
        cudaLaunchKernelEx(&cfg, k_build, ei);
    }

    // join: fin1 needs encode's Ms1
    cudaStreamWaitEvent(0, ev_join, 0);

    {
        cudaLaunchConfig_t cfg = {};
        cfg.gridDim = dim3(nb_n); cfg.blockDim = dim3(TB); cfg.stream = 0;
        cfg.attrs = &pdl; cfg.numAttrs = 1;
        cudaLaunchKernelEx(&cfg, k_fin1, w2, b2);
    }
    {
        cudaLaunchConfig_t cfg = {};
        cfg.gridDim = dim3(nb_n); cfg.blockDim = dim3(TB); cfg.stream = 0;
        cfg.attrs = &pdl; cfg.numAttrs = 1;
        cudaLaunchKernelEx(&cfg, k_fin2, we1, be1);
    }
    {
        cudaLaunchConfig_t cfg = {};
        cfg.gridDim = dim3(nb_e2); cfg.blockDim = dim3(EO_TB); cfg.stream = 0;
        cfg.attrs = &pdl; cfg.numAttrs = 1;
        cudaLaunchKernelEx(&cfg, k_edge_out, ei, eattr, we1, we2, be2, out);
    }
}